// round 7
// baseline (speedup 1.0000x reference)
#include <cuda_runtime.h>
#include <math.h>
#include <stdint.h>

#define MAXT  10000
#define BATCH 4096

#define LOG_GAMMA_F  0.019802627296179712f
#define ALPHA_F     (-1.0050335853501441e-05f)
#define INIT_LOGW_D (-1.3943265262)
#define INIT_LOGP_D (-6.907755278982137)
#define EPSF 1e-12f

#define GRID 148
#define BLK  256
#define SBLK 40          // scan chunks (40*256 = 10240 >= MAXT)
#define DCH  16          // detect t-chunk rows (divides MAXT exactly -> no edge chunk)
#define DGX  4           // batch slices (4 * 256thr * 4elem = 4096)

__device__ float  g_csum[SBLK];
__device__ float  g_dsum[SBLK];
__device__ float  g_rsum[SBLK];
__device__ float  g_rinc[MAXT];     // block-local INCLUSIVE prefix of r
__device__ double g_rpre[SBLK];     // cross-block EXCLUSIVE prefix of r-sums
__device__ float2 g_thr[MAXT];      // {Rthr, u2thr}
__device__ int    g_death[BATCH];
__device__ int    g_tactive = MAXT;
__device__ unsigned g_cnt0, g_cnt1, g_cnt2, g_done;     // zero-init; reset by finalizer
__device__ volatile unsigned g_flag0, g_flag1, g_flag2; // zero-init; reset by finalizer

// ---- grid-wide spin barrier (all GRID CTAs co-resident by construction) ----
__device__ __forceinline__ void gbar(unsigned* cnt, volatile unsigned* flag, int tid) {
    __syncthreads();
    if (tid == 0) {
        __threadfence();
        if (atomicAdd(cnt, 1u) == GRID - 1) {
            *flag = 1u;
        } else {
            while (*flag == 0u) { }
        }
        __threadfence();
    }
    __syncthreads();
}

// ---- 64-thread double-sum of first B entries of a 40-float smem array ----
__device__ __forceinline__ double par_sum40(const float* vals, int B,
                                            double* wtmp, double* res, int tid) {
    __syncthreads();
    double x = 0.0;
    if (tid < SBLK && tid < B) x = (double)vals[tid];
    if (tid < 64) {
        #pragma unroll
        for (int o = 16; o > 0; o >>= 1) x += __shfl_down_sync(0xffffffffu, x, o);
        if ((tid & 31) == 0) wtmp[tid >> 5] = x;
    }
    __syncthreads();
    if (tid == 0) *res = wtmp[0] + wtmp[1];
    __syncthreads();
    return *res;
}

// ---- block-local inclusive scan (256 threads, fp32) ----
__device__ __forceinline__ float blk_scan_incl(float v, int tid, float* wsm) {
    __syncthreads();
    float x = v;
    #pragma unroll
    for (int o = 1; o < 32; o <<= 1) {
        float y = __shfl_up_sync(0xffffffffu, x, o);
        if ((tid & 31) >= o) x += y;
    }
    int wid = tid >> 5, lid = tid & 31;
    if (lid == 31) wsm[wid] = x;
    __syncthreads();
    if (wid == 0) {
        float w = (lid < 8) ? wsm[lid] : 0.0f;
        #pragma unroll
        for (int o = 1; o < 8; o <<= 1) {
            float y = __shfl_up_sync(0xffffffffu, w, o);
            if (lid >= o) w += y;
        }
        if (lid < 8) wsm[lid] = w;
    }
    __syncthreads();
    float base = (wid == 0) ? 0.0f : wsm[wid - 1];
    return base + x;
}

__global__ void xrisk_kernel(const float* __restrict__ acts,
                             const float* __restrict__ u1,
                             const float* __restrict__ u2,
                             float* __restrict__ out) {
    __shared__ float wsm[8];
    __shared__ float sv[SBLK];
    __shared__ double wtmp[2];
    __shared__ double sres;
    __shared__ float sR[DCH], sU[DCH];
    __shared__ int s_fin;
    __shared__ double sh[8];

    int tid = threadIdx.x, bid = blockIdx.x;
    bool scanb = (bid < SBLK);
    int t = bid * BLK + tid;                 // scan element for scan blocks

    // ---------- Phase 1: per-chunk c sums; death reset ----------
    float f = 0.0f, c = 0.0f;
    if (scanb) {
        if (t < MAXT) {
            f = __expf(__ldg(acts + t));
            c = LOG_GAMMA_F + log1pf(-f);
        }
        float x = c;
        #pragma unroll
        for (int o = 16; o > 0; o >>= 1) x += __shfl_down_sync(0xffffffffu, x, o);
        if ((tid & 31) == 0) wsm[tid >> 5] = x;
        __syncthreads();
        if (tid == 0) {
            float s = 0.0f;
            #pragma unroll
            for (int i = 0; i < 8; i++) s += wsm[i];
            g_csum[bid] = s;
        }
    } else if (bid >= SBLK && bid < SBLK + BATCH / BLK) {
        g_death[(bid - SBLK) * BLK + tid] = MAXT;
    }
    gbar(&g_cnt0, &g_flag0, tid);

    // ---------- Phase 2: d/r block prefixes ----------
    float d = 0.0f, r = 0.0f, dinc = 0.0f;
    if (scanb) {
        if (tid < SBLK) sv[tid] = g_csum[tid];
        double cbase = par_sum40(sv, bid, wtmp, &sres, tid);
        float cinc = blk_scan_incl(c, tid, wsm);
        float lwb = (float)(INIT_LOGW_D + cbase) + (cinc - c);  // logw BEFORE step t
        if (t < MAXT) {
            // logw grows to ~196; clamp exp arg (only the provably-dead region)
            d = (ALPHA_F * f) * __expf(fminf(lwb, 30.0f));
            r = __expf((lwb + c) * 0.001f);     // exp(new_logw/1000)
        }
        dinc = blk_scan_incl(d, tid, wsm);
        float rinc = blk_scan_incl(r, tid, wsm);
        if (t < MAXT) g_rinc[t] = rinc;
        if (tid == BLK - 1) {
            g_dsum[bid] = dinc;
            g_rsum[bid] = rinc;
        }
    }
    gbar(&g_cnt1, &g_flag1, tid);

    // ---------- Phase 3: thresholds + tactive + rpre ----------
    if (scanb) {
        if (tid < SBLK) sv[tid] = g_dsum[tid];
        double dbase = par_sum40(sv, bid, wtmp, &sres, tid);
        if (tid < SBLK) sv[tid] = g_rsum[tid];
        double rpre = par_sum40(sv, bid, wtmp, &sres, tid);
        if (tid == 0) g_rpre[bid] = rpre;

        float R = 0.0f;
        if (t < MAXT) {
            float lp = (float)(INIT_LOGP_D + dbase) + (dinc - d);  // logp BEFORE step t
            float p = __expf(fmaxf(lp, -87.0f));
            R = p * (1.0f + p * (1.0f + p)) - 1e-12f;              // p/(1-p) - eps
            float U = fmaf(-27.66f, R, 0.99999988f);               // conservative bound
            g_thr[t] = make_float2(R, U);
        }
        int bad = (t < MAXT && R < 1e-9f) ? t : 0x7fffffff;
        #pragma unroll
        for (int o = 16; o > 0; o >>= 1) bad = min(bad, __shfl_down_sync(0xffffffffu, bad, o));
        __shared__ int sbad[8];
        if ((tid & 31) == 0) sbad[tid >> 5] = bad;
        __syncthreads();
        if (tid == 0) {
            int m = 0x7fffffff;
            #pragma unroll
            for (int i = 0; i < 8; i++) m = min(m, sbad[i]);
            if (m != 0x7fffffff) atomicMin(&g_tactive, m);
        }
    }
    gbar(&g_cnt2, &g_flag2, tid);

    // ---------- Phase 4: detect. DCH divides MAXT -> every chunk is full; rows past
    // t_active are harmless (R<1e-9 => ey > any u2 float < 1), so NO inner guards. ----------
    {
        int ta = g_tactive;
        int nchunks = (ta + DCH - 1) / DCH;
        int nitems = nchunks * DGX;
        for (int item = bid; item < nitems; item += GRID) {
            int t0 = (item >> 2) * DCH;
            int xs = item & 3;
            __syncthreads();
            if (tid < DCH) {
                float2 th = g_thr[t0 + tid];
                sR[tid] = th.x; sU[tid] = th.y;
            }
            __syncthreads();

            int b0 = xs * 1024 + tid * 4;
            const float* p2 = u2 + (size_t)t0 * BATCH + b0;
            const float* p1 = u1 + (size_t)t0 * BATCH + b0;

            // batched loads: 16 independent LDG.128 in flight per thread
            float4 v[DCH];
            #pragma unroll
            for (int i = 0; i < DCH; i++)
                v[i] = __ldg((const float4*)(p2 + (size_t)i * BATCH));

            int ft0 = 0x7fffffff, ft1 = 0x7fffffff, ft2 = 0x7fffffff, ft3 = 0x7fffffff;
            #pragma unroll
            for (int i = 0; i < DCH; i++) {
                float U = sU[i];
                float mx = fmaxf(fmaxf(v[i].x, v[i].y), fmaxf(v[i].z, v[i].w));
                if (mx + EPSF > U) {                 // rare (~3%/component)
                    float R = sR[i];
                    const float* q1 = p1 + (size_t)i * BATCH;
                    #define XR_CHECK(comp, off, ftv)                                      \
                        if (comp + EPSF > U) {                                            \
                            float v1 = __ldg(q1 + off);                                   \
                            float L1 = logf(v1 + EPSF);                                   \
                            float y = R * L1;                                             \
                            float ey = 1.0f + y * (1.0f + y * (0.5f + y *                 \
                                       (0.16666667f + y * 0.04166667f)));                 \
                            if (comp + EPSF > ey) ftv = min(ftv, t0 + i);                 \
                        }
                    XR_CHECK(v[i].x, 0, ft0)
                    XR_CHECK(v[i].y, 1, ft1)
                    XR_CHECK(v[i].z, 2, ft2)
                    XR_CHECK(v[i].w, 3, ft3)
                    #undef XR_CHECK
                }
            }
            if (ft0 != 0x7fffffff) atomicMin(&g_death[b0 + 0], ft0);
            if (ft1 != 0x7fffffff) atomicMin(&g_death[b0 + 1], ft1);
            if (ft2 != 0x7fffffff) atomicMin(&g_death[b0 + 2], ft2);
            if (ft3 != 0x7fffffff) atomicMin(&g_death[b0 + 3], ft3);
        }
    }

    // ---------- Arrive-only ticket: last block finalizes ----------
    __syncthreads();
    if (tid == 0) {
        __threadfence();
        unsigned o = atomicAdd(&g_done, 1u);
        s_fin = (o == GRID - 1);
    }
    __syncthreads();
    if (!s_fin) return;

    __threadfence();
    __shared__ double rpre_s[SBLK];
    if (tid < SBLK) rpre_s[tid] = g_rpre[tid];
    __syncthreads();

    double acc = 0.0;
    #pragma unroll
    for (int k = 0; k < BATCH / BLK; k++) {
        int b = k * BLK + tid;
        int td = g_death[b];
        if (td > MAXT) td = MAXT;
        if (td > 0) {
            int tm = td - 1;
            acc += rpre_s[tm >> 8] + (double)g_rinc[tm];   // S[td-1]
        }
    }
    #pragma unroll
    for (int o = 16; o > 0; o >>= 1) acc += __shfl_down_sync(0xffffffffu, acc, o);
    if ((tid & 31) == 0) sh[tid >> 5] = acc;
    __syncthreads();
    if (tid == 0) {
        double s = 0.0;
        #pragma unroll
        for (int i = 0; i < 8; i++) s += sh[i];
        out[0] = (float)(s / (double)BATCH);
        // reset barrier/launch state for the next graph replay
        g_cnt0 = 0u; g_cnt1 = 0u; g_cnt2 = 0u; g_done = 0u;
        g_flag0 = 0u; g_flag1 = 0u; g_flag2 = 0u;
        g_tactive = MAXT;
    }
}

extern "C" void kernel_launch(void* const* d_in, const int* in_sizes, int n_in,
                              void* d_out, int out_size) {
    const float* acts = (const float*)d_in[0];
    const float* u1   = (const float*)d_in[1];
    const float* u2   = (const float*)d_in[2];
    (void)in_sizes; (void)n_in; (void)out_size;
    xrisk_kernel<<<GRID, BLK>>>(acts, u1, u2, (float*)d_out);
}

// round 9
// speedup vs baseline: 1.4847x; 1.4847x over previous
#include <cuda_runtime.h>
#include <math.h>
#include <stdint.h>

#define MAXT  10000
#define BATCH 4096

#define LOG_GAMMA_F  0.019802627296179712f
#define ALPHA_F     (-1.0050335853501441e-05f)
#define INIT_LOGW_D (-1.3943265262)
#define INIT_LOGP_D (-6.907755278982137)
#define EPSF 1e-12f

#define SBLK 40          // scan chunks (40*256 = 10240 >= MAXT)
#define STH  256
#define DCH  32          // detect rows per block (two 16-deep load waves)
#define DGX  4           // batch slices (4 * 256thr * 4elem = 4096)
#define DGY  ((MAXT + DCH - 1) / DCH)   // 313
#define FBLK 16

__device__ float  g_csum[SBLK];
__device__ float  g_dsum[SBLK];
__device__ float  g_rsum[SBLK];
__device__ float  g_rinc[MAXT];     // block-local INCLUSIVE prefix of r
__device__ double g_rpre[SBLK];     // cross-block EXCLUSIVE prefix of r-sums
__device__ float2 g_thr[MAXT];      // {Rthr, u2thr}
__device__ int    g_death[BATCH];
__device__ int    g_tactive = MAXT;
__device__ double g_acc;
__device__ unsigned g_tick;
__device__ unsigned g_bar0, g_bar1;             // zero-init; reset by final
__device__ volatile unsigned g_bf0, g_bf1;      // zero-init; reset by final

// ---- 40-block spin barrier (co-resident: grid == SBLK << #SM) ----
__device__ __forceinline__ void gbar40(unsigned* cnt, volatile unsigned* flag, int tid) {
    __syncthreads();
    if (tid == 0) {
        __threadfence();
        if (atomicAdd(cnt, 1u) == SBLK - 1) *flag = 1u;
        else while (*flag == 0u) { }
        __threadfence();
    }
    __syncthreads();
}

// ---- 64-thread double-sum of first B entries of a 40-float smem array ----
__device__ __forceinline__ double par_sum40(const float* vals, int B,
                                            double* wtmp, double* res, int tid) {
    __syncthreads();
    double x = 0.0;
    if (tid < SBLK && tid < B) x = (double)vals[tid];
    if (tid < 64) {
        #pragma unroll
        for (int o = 16; o > 0; o >>= 1) x += __shfl_down_sync(0xffffffffu, x, o);
        if ((tid & 31) == 0) wtmp[tid >> 5] = x;
    }
    __syncthreads();
    if (tid == 0) *res = wtmp[0] + wtmp[1];
    __syncthreads();
    return *res;
}

// ---- block-local inclusive scan (256 threads, fp32) ----
__device__ __forceinline__ float blk_scan_incl(float v, int tid, float* wsm) {
    __syncthreads();
    float x = v;
    #pragma unroll
    for (int o = 1; o < 32; o <<= 1) {
        float y = __shfl_up_sync(0xffffffffu, x, o);
        if ((tid & 31) >= o) x += y;
    }
    int wid = tid >> 5, lid = tid & 31;
    if (lid == 31) wsm[wid] = x;
    __syncthreads();
    if (wid == 0) {
        float w = (lid < 8) ? wsm[lid] : 0.0f;
        #pragma unroll
        for (int o = 1; o < 8; o <<= 1) {
            float y = __shfl_up_sync(0xffffffffu, w, o);
            if (lid >= o) w += y;
        }
        if (lid < 8) wsm[lid] = w;
    }
    __syncthreads();
    float base = (wid == 0) ? 0.0f : wsm[wid - 1];
    return base + x;
}

// ---------------- K1: full scalar scan (40 blocks, internal barriers) ----------------
__global__ void scan_kernel(const float* __restrict__ acts) {
    __shared__ float wsm[8];
    __shared__ float sv[SBLK];
    __shared__ double wtmp[2];
    __shared__ double sres;
    __shared__ int sbad[8];
    int tid = threadIdx.x, bid = blockIdx.x;
    int t = bid * STH + tid;

    // phase A: per-chunk c sums (+ death reset: 40*256 = 10240 > 4096 covered)
    float f = 0.0f, c = 0.0f;
    if (t < MAXT) {
        f = __expf(__ldg(acts + t));
        c = LOG_GAMMA_F + log1pf(-f);
    }
    float x = c;
    #pragma unroll
    for (int o = 16; o > 0; o >>= 1) x += __shfl_down_sync(0xffffffffu, x, o);
    if ((tid & 31) == 0) wsm[tid >> 5] = x;
    __syncthreads();
    if (tid == 0) {
        float s = 0.0f;
        #pragma unroll
        for (int i = 0; i < 8; i++) s += wsm[i];
        g_csum[bid] = s;
    }
    if (t < BATCH) g_death[t] = MAXT;
    gbar40(&g_bar0, &g_bf0, tid);

    // phase B: cbase -> logw; d, r elementwise + block prefixes
    if (tid < SBLK) sv[tid] = g_csum[tid];
    double cbase = par_sum40(sv, bid, wtmp, &sres, tid);
    float cinc = blk_scan_incl(c, tid, wsm);
    float lwb = (float)(INIT_LOGW_D + cbase) + (cinc - c);  // logw BEFORE step t
    float d = 0.0f, r = 0.0f;
    if (t < MAXT) {
        // logw grows to ~196; clamp exp arg (only the provably-dead region)
        d = (ALPHA_F * f) * __expf(fminf(lwb, 30.0f));
        r = __expf((lwb + c) * 0.001f);                     // exp(new_logw/1000)
    }
    float dinc = blk_scan_incl(d, tid, wsm);
    float rinc = blk_scan_incl(r, tid, wsm);
    if (t < MAXT) g_rinc[t] = rinc;
    if (tid == STH - 1) { g_dsum[bid] = dinc; g_rsum[bid] = rinc; }
    gbar40(&g_bar1, &g_bf1, tid);

    // phase C: thresholds, tactive, rpre
    if (tid < SBLK) sv[tid] = g_dsum[tid];
    double dbase = par_sum40(sv, bid, wtmp, &sres, tid);
    if (tid < SBLK) sv[tid] = g_rsum[tid];
    double rpre = par_sum40(sv, bid, wtmp, &sres, tid);
    if (tid == 0) g_rpre[bid] = rpre;

    float R = 0.0f;
    if (t < MAXT) {
        float lp = (float)(INIT_LOGP_D + dbase) + (dinc - d);   // logp BEFORE step t
        float p = __expf(fmaxf(lp, -87.0f));
        R = p * (1.0f + p * (1.0f + p)) - 1e-12f;               // p/(1-p) - eps
        float U = fmaf(-27.66f, R, 0.99999988f);                // conservative bound
        g_thr[t] = make_float2(R, U);
    }
    int bad = (t < MAXT && R < 1e-9f) ? t : 0x7fffffff;
    #pragma unroll
    for (int o = 16; o > 0; o >>= 1) bad = min(bad, __shfl_down_sync(0xffffffffu, bad, o));
    if ((tid & 31) == 0) sbad[tid >> 5] = bad;
    __syncthreads();
    if (tid == 0) {
        int m = 0x7fffffff;
        #pragma unroll
        for (int i = 0; i < 8; i++) m = min(m, sbad[i]);
        if (m != 0x7fffffff) atomicMin(&g_tactive, m);
    }
}

// ---------------- K2: detect first deaths (high-occupancy, stackable CTAs) ----------------
__global__ void detect_kernel(const float* __restrict__ u1, const float* __restrict__ u2) {
    int t0 = blockIdx.y * DCH;
    if (t0 >= g_tactive) return;          // broadcast read; ~90% of blocks exit here

    __shared__ float sR[DCH], sU[DCH];
    int tid = threadIdx.x;
    if (tid < DCH) {
        int tt = t0 + tid;
        float2 th = (tt < MAXT) ? g_thr[tt] : make_float2(0.0f, 2.0f);
        sR[tid] = th.x; sU[tid] = th.y;
    }
    __syncthreads();

    int b0 = blockIdx.x * 1024 + tid * 4;
    const float* p2 = u2 + (size_t)t0 * BATCH + b0;
    const float* p1 = u1 + (size_t)t0 * BATCH + b0;
    int ft0 = 0x7fffffff, ft1 = 0x7fffffff, ft2 = 0x7fffffff, ft3 = 0x7fffffff;

    // rows past MAXT edge: DGY*DCH = 10016 > 10000, last chunk has 16 ghost rows.
    // Guard only the second wave of the final chunk (t0 == 9984).
    int nrow2 = (t0 + DCH <= MAXT) ? 16 : (MAXT - t0 - 16);   // rows in wave 2 (16 normally)

    #pragma unroll
    for (int h = 0; h < 2; h++) {
        float4 v[16];
        int lim = (h == 0) ? 16 : nrow2;
        #pragma unroll
        for (int i = 0; i < 16; i++) {
            int row = h * 16 + i;
            v[i] = (i < lim) ? __ldg((const float4*)(p2 + (size_t)row * BATCH))
                             : make_float4(0.f, 0.f, 0.f, 0.f);
        }
        #pragma unroll
        for (int i = 0; i < 16; i++) {
            if (i >= lim) break;
            int row = h * 16 + i;
            float U = sU[row];
            float mx = fmaxf(fmaxf(v[i].x, v[i].y), fmaxf(v[i].z, v[i].w));
            if (mx + EPSF > U) {                  // rare (~3%/component)
                float R = sR[row];
                const float* q1 = p1 + (size_t)row * BATCH;
                #define XR_CHECK(comp, off, ftv)                                      \
                    if (comp + EPSF > U) {                                            \
                        float v1 = __ldg(q1 + off);                                   \
                        float L1 = logf(v1 + EPSF);                                   \
                        float y = R * L1;                                             \
                        float ey = 1.0f + y * (1.0f + y * (0.5f + y *                 \
                                   (0.16666667f + y * 0.04166667f)));                 \
                        if (comp + EPSF > ey) ftv = min(ftv, t0 + row);               \
                    }
                XR_CHECK(v[i].x, 0, ft0)
                XR_CHECK(v[i].y, 1, ft1)
                XR_CHECK(v[i].z, 2, ft2)
                XR_CHECK(v[i].w, 3, ft3)
                #undef XR_CHECK
            }
        }
    }
    if (ft0 != 0x7fffffff) atomicMin(&g_death[b0 + 0], ft0);
    if (ft1 != 0x7fffffff) atomicMin(&g_death[b0 + 1], ft1);
    if (ft2 != 0x7fffffff) atomicMin(&g_death[b0 + 2], ft2);
    if (ft3 != 0x7fffffff) atomicMin(&g_death[b0 + 3], ft3);
}

// ---------------- K3: finalize (16 blocks, precomputed rpre) ----------------
__global__ void final_kernel(float* __restrict__ out) {
    __shared__ double rpre_s[SBLK];
    __shared__ double sh[8];
    __shared__ int s_last;
    int tid = threadIdx.x;
    if (tid < SBLK) rpre_s[tid] = g_rpre[tid];
    __syncthreads();

    int b = blockIdx.x * 256 + tid;
    int td = g_death[b];
    if (td > MAXT) td = MAXT;
    double v = 0.0;
    if (td > 0) {
        int tm = td - 1;
        v = rpre_s[tm >> 8] + (double)g_rinc[tm];   // S[td-1]
    }
    #pragma unroll
    for (int o = 16; o > 0; o >>= 1) v += __shfl_down_sync(0xffffffffu, v, o);
    if ((tid & 31) == 0) sh[tid >> 5] = v;
    __syncthreads();
    if (tid == 0) {
        double s = 0.0;
        #pragma unroll
        for (int i = 0; i < 8; i++) s += sh[i];
        atomicAdd(&g_acc, s);
        __threadfence();
        s_last = (atomicAdd(&g_tick, 1u) == FBLK - 1);
    }
    __syncthreads();
    if (tid == 0 && s_last) {
        double tot = atomicAdd(&g_acc, 0.0);
        out[0] = (float)(tot / (double)BATCH);
        // reset ALL persistent state for the next graph replay
        g_acc = 0.0; g_tick = 0u;
        g_bar0 = 0u; g_bar1 = 0u;
        g_bf0 = 0u;  g_bf1 = 0u;
        g_tactive = MAXT;
    }
}

extern "C" void kernel_launch(void* const* d_in, const int* in_sizes, int n_in,
                              void* d_out, int out_size) {
    const float* acts = (const float*)d_in[0];
    const float* u1   = (const float*)d_in[1];
    const float* u2   = (const float*)d_in[2];
    (void)in_sizes; (void)n_in; (void)out_size;

    scan_kernel<<<SBLK, STH>>>(acts);
    dim3 grid(DGX, DGY);
    detect_kernel<<<grid, 256>>>(u1, u2);
    final_kernel<<<FBLK, 256>>>((float*)d_out);
}